// round 10
// baseline (speedup 1.0000x reference)
#include <cuda_runtime.h>

// FeedForwardQuantum: out = relu(cos(x+theta) @ W1 + b1) @ W2 + b2
// x: [524288, 8] fp32, W1: [8,32], W2: [32,8].
// R4 finding: doubling occupancy didn't move dur -> issue-slot overhead bound
// (~1200 issues per 2-row chunk vs ~640 math ops). R5: kill the overhead:
//  - weights pre-duplicated as 64-bit (w,w) pairs in __constant__ (LDC.128 loads
//    2 FFMA2-ready operands; deletes 16 dup-MOVs per f; enables UR promotion)
//  - all packed state carried as raw u64 through "l"-constraint fma.rn.f32x2
//  - f-loop interleaved x2 for GEMM1 chain ILP

#define EDIM 8
#define FDIM 32
#define RPT 2
#define BLOCK 128
typedef unsigned long long ULL;

struct CW {
    ulonglong2 w1p[FDIM][4];  // [f][j]: dup pairs of w1[2j][f], w1[2j+1][f]
    ulonglong2 w2p[FDIM][4];  // [f][j]: dup pairs of w2[f][2j], w2[f][2j+1]
    ULL b1d[FDIM];            // dup pair of b1[f]
    ULL b2d[EDIM];            // dup pair of b2[e]
};

__constant__ CW c_w;
__device__   CW g_s;

__device__ __forceinline__ ULL ffma2(ULL a, ULL b, ULL c) {
    ULL d;
    asm("fma.rn.f32x2 %0, %1, %2, %3;" : "=l"(d) : "l"(a), "l"(b), "l"(c));
    return d;
}
__device__ __forceinline__ ULL pack2(float lo, float hi) {
    ULL r; asm("mov.b64 %0, {%1, %2};" : "=l"(r) : "f"(lo), "f"(hi)); return r;
}
__device__ __forceinline__ float2 unpack2(ULL v) {
    float2 p; asm("mov.b64 {%0, %1}, %2;" : "=f"(p.x), "=f"(p.y) : "l"(v)); return p;
}
__device__ __forceinline__ ULL relu2(ULL v) {
    float2 p = unpack2(v);
    p.x = fmaxf(p.x, 0.0f);
    p.y = fmaxf(p.y, 0.0f);
    return pack2(p.x, p.y);
}

// accurate-enough cos for |a| <~ 16: 2-term 2pi reduction + MUFU cos
__device__ __forceinline__ float fast_cos(float a) {
    const float INV_2PI = 0.15915494309189535f;
    const float PI2_HI  = 6.28318548202514648f;
    const float PI2_LO  = 1.7484555e-7f;
    float k = rintf(a * INV_2PI);
    float r = fmaf(k, -PI2_HI, a);
    r = fmaf(k, PI2_LO, r);
    return __cosf(r);
}

__global__ void ffq_prep(const float* __restrict__ w1, const float* __restrict__ b1,
                         const float* __restrict__ w2, const float* __restrict__ b2)
{
    int f = threadIdx.x;
    if (f < FDIM) {
#pragma unroll
        for (int j = 0; j < 4; j++) {
            float a = w1[(2 * j)     * FDIM + f];
            float b = w1[(2 * j + 1) * FDIM + f];
            g_s.w1p[f][j] = make_ulonglong2(pack2(a, a), pack2(b, b));
            float c = w2[f * EDIM + 2 * j];
            float d = w2[f * EDIM + 2 * j + 1];
            g_s.w2p[f][j] = make_ulonglong2(pack2(c, c), pack2(d, d));
        }
        float bb = b1[f];
        g_s.b1d[f] = pack2(bb, bb);
        if (f < EDIM) { float v = b2[f]; g_s.b2d[f] = pack2(v, v); }
    }
}

__global__ void __launch_bounds__(BLOCK)
ffq_kernel(const float* __restrict__ x, const float* __restrict__ theta,
           float* __restrict__ out, long long nrows)
{
    const int t = threadIdx.x;
    const long long idx  = (long long)blockIdx.x * BLOCK + t;
    const long long row0 = idx * RPT;
    if (row0 >= nrows) return;

    float th[EDIM];
#pragma unroll
    for (int e = 0; e < EDIM; e++) th[e] = __ldg(theta + e);

    if (row0 + RPT <= nrows) {
        // ---- fast path: 2 rows; q[e] = pack(cos row0, cos row1) ----
        const float4* xp = reinterpret_cast<const float4*>(x + row0 * EDIM);
        float4 a0 = xp[0], a1 = xp[1];   // row 0
        float4 b0 = xp[2], b1v = xp[3];  // row 1

        ULL q[EDIM];
        q[0] = pack2(fast_cos(a0.x + th[0]), fast_cos(b0.x + th[0]));
        q[1] = pack2(fast_cos(a0.y + th[1]), fast_cos(b0.y + th[1]));
        q[2] = pack2(fast_cos(a0.z + th[2]), fast_cos(b0.z + th[2]));
        q[3] = pack2(fast_cos(a0.w + th[3]), fast_cos(b0.w + th[3]));
        q[4] = pack2(fast_cos(a1.x + th[4]), fast_cos(b1v.x + th[4]));
        q[5] = pack2(fast_cos(a1.y + th[5]), fast_cos(b1v.y + th[5]));
        q[6] = pack2(fast_cos(a1.z + th[6]), fast_cos(b1v.z + th[6]));
        q[7] = pack2(fast_cos(a1.w + th[7]), fast_cos(b1v.w + th[7]));

        ULL acc[EDIM];
#pragma unroll
        for (int e = 0; e < EDIM; e++) acc[e] = c_w.b2d[e];

#pragma unroll
        for (int f = 0; f < FDIM; f += 2) {
            // GEMM1: two independent depth-8 chains (f and f+1) for ILP
            ulonglong2 wa0 = c_w.w1p[f][0],     wa1 = c_w.w1p[f][1];
            ulonglong2 wa2 = c_w.w1p[f][2],     wa3 = c_w.w1p[f][3];
            ulonglong2 wb0 = c_w.w1p[f + 1][0], wb1 = c_w.w1p[f + 1][1];
            ulonglong2 wb2 = c_w.w1p[f + 1][2], wb3 = c_w.w1p[f + 1][3];

            ULL h0 = ffma2(q[0], wa0.x, c_w.b1d[f]);
            ULL h1 = ffma2(q[0], wb0.x, c_w.b1d[f + 1]);
            h0 = ffma2(q[1], wa0.y, h0);  h1 = ffma2(q[1], wb0.y, h1);
            h0 = ffma2(q[2], wa1.x, h0);  h1 = ffma2(q[2], wb1.x, h1);
            h0 = ffma2(q[3], wa1.y, h0);  h1 = ffma2(q[3], wb1.y, h1);
            h0 = ffma2(q[4], wa2.x, h0);  h1 = ffma2(q[4], wb2.x, h1);
            h0 = ffma2(q[5], wa2.y, h0);  h1 = ffma2(q[5], wb2.y, h1);
            h0 = ffma2(q[6], wa3.x, h0);  h1 = ffma2(q[6], wb3.x, h1);
            h0 = ffma2(q[7], wa3.y, h0);  h1 = ffma2(q[7], wb3.y, h1);

            h0 = relu2(h0);
            h1 = relu2(h1);

            ulonglong2 va0 = c_w.w2p[f][0],     va1 = c_w.w2p[f][1];
            ulonglong2 va2 = c_w.w2p[f][2],     va3 = c_w.w2p[f][3];
            ulonglong2 vb0 = c_w.w2p[f + 1][0], vb1 = c_w.w2p[f + 1][1];
            ulonglong2 vb2 = c_w.w2p[f + 1][2], vb3 = c_w.w2p[f + 1][3];

            acc[0] = ffma2(h0, va0.x, acc[0]);  acc[0] = ffma2(h1, vb0.x, acc[0]);
            acc[1] = ffma2(h0, va0.y, acc[1]);  acc[1] = ffma2(h1, vb0.y, acc[1]);
            acc[2] = ffma2(h0, va1.x, acc[2]);  acc[2] = ffma2(h1, vb1.x, acc[2]);
            acc[3] = ffma2(h0, va1.y, acc[3]);  acc[3] = ffma2(h1, vb1.y, acc[3]);
            acc[4] = ffma2(h0, va2.x, acc[4]);  acc[4] = ffma2(h1, vb2.x, acc[4]);
            acc[5] = ffma2(h0, va2.y, acc[5]);  acc[5] = ffma2(h1, vb2.y, acc[5]);
            acc[6] = ffma2(h0, va3.x, acc[6]);  acc[6] = ffma2(h1, vb3.x, acc[6]);
            acc[7] = ffma2(h0, va3.y, acc[7]);  acc[7] = ffma2(h1, vb3.y, acc[7]);
        }

        float2 p0 = unpack2(acc[0]), p1 = unpack2(acc[1]);
        float2 p2 = unpack2(acc[2]), p3 = unpack2(acc[3]);
        float2 p4 = unpack2(acc[4]), p5 = unpack2(acc[5]);
        float2 p6 = unpack2(acc[6]), p7 = unpack2(acc[7]);

        float4* op = reinterpret_cast<float4*>(out + row0 * EDIM);
        op[0] = make_float4(p0.x, p1.x, p2.x, p3.x);
        op[1] = make_float4(p4.x, p5.x, p6.x, p7.x);
        op[2] = make_float4(p0.y, p1.y, p2.y, p3.y);
        op[3] = make_float4(p4.y, p5.y, p6.y, p7.y);
    } else {
        // ---- tail: scalar per-row fallback (reads lo halves of dup pairs) ----
        for (long long r = row0; r < nrows; r++) {
            float q[EDIM];
#pragma unroll
            for (int e = 0; e < EDIM; e++) q[e] = fast_cos(x[r * EDIM + e] + th[e]);
            float o[EDIM];
#pragma unroll
            for (int e = 0; e < EDIM; e++)
                o[e] = ((const float*)&c_w.b2d[e])[0];
            for (int f = 0; f < FDIM; f++) {
                float h = ((const float*)&c_w.b1d[f])[0];
#pragma unroll
                for (int e = 0; e < EDIM; e++)
                    h = fmaf(q[e], ((const float*)&c_w.w1p[f][e >> 1])[(e & 1) * 2], h);
                h = fmaxf(h, 0.0f);
#pragma unroll
                for (int e = 0; e < EDIM; e++)
                    o[e] = fmaf(h, ((const float*)&c_w.w2p[f][e >> 1])[(e & 1) * 2], o[e]);
            }
#pragma unroll
            for (int e = 0; e < EDIM; e++) out[r * EDIM + e] = o[e];
        }
    }
}

extern "C" void kernel_launch(void* const* d_in, const int* in_sizes, int n_in,
                              void* d_out, int out_size) {
    const float* x     = (const float*)d_in[0];
    const float* theta = (const float*)d_in[1];
    const float* w1    = (const float*)d_in[2];
    const float* b1    = (const float*)d_in[3];
    const float* w2    = (const float*)d_in[4];
    const float* b2    = (const float*)d_in[5];
    float* out = (float*)d_out;

    long long nrows = (long long)in_sizes[0] / EDIM;
    long long nthreads = (nrows + RPT - 1) / RPT;
    int blocks = (int)((nthreads + BLOCK - 1) / BLOCK);

    ffq_prep<<<1, 64>>>(w1, b1, w2, b2);

    void *c_ptr = nullptr, *s_ptr = nullptr;
    cudaGetSymbolAddress(&c_ptr, c_w);
    cudaGetSymbolAddress(&s_ptr, g_s);
    cudaMemcpyAsync(c_ptr, s_ptr, sizeof(CW), cudaMemcpyDeviceToDevice, 0);

    ffq_kernel<<<blocks, BLOCK>>>(x, theta, out, nrows);
}